// round 7
// baseline (speedup 1.0000x reference)
#include <cuda_runtime.h>
#include <math.h>

#define NB 8192      // batch rows
#define ND 1024      // feature dim
#define NG 8         // tile count
#define TOTAL (NB * ND)          // 8,388,608 floats
#define TOTAL4 (TOTAL / 4)       // 2,097,152 float4
#define R1_BLOCKS 1024
#define R1_THREADS 256
#define ROWS_PB 4                // rows per block in K3
#define K3_THREADS 128           // 128 thr x 8 floats = 1024 = one row

__device__ float g_partials[R1_BLOCKS];
__device__ float g_mean_scale[2];         // [0] = mean, [1] = sigmoid(wp)
__device__ unsigned int g_ticket = 0;     // reset in-kernel each launch

// 256-bit load/store helpers (sm_100a+)
__device__ __forceinline__ void ldg256(const float* p, float* v) {
    asm("ld.global.nc.v8.f32 {%0,%1,%2,%3,%4,%5,%6,%7}, [%8];"
        : "=f"(v[0]), "=f"(v[1]), "=f"(v[2]), "=f"(v[3]),
          "=f"(v[4]), "=f"(v[5]), "=f"(v[6]), "=f"(v[7])
        : "l"(p));
}
__device__ __forceinline__ void stg256_cs(float* p, const float* v) {
    asm volatile("st.global.cs.v8.f32 [%0], {%1,%2,%3,%4,%5,%6,%7,%8};"
        :: "l"(p),
           "f"(v[0]), "f"(v[1]), "f"(v[2]), "f"(v[3]),
           "f"(v[4]), "f"(v[5]), "f"(v[6]), "f"(v[7])
        : "memory");
}

// ---------------------------------------------------------------------------
// K1: per-block partial sums; LAST block reduces the 1024 partials in a
// fixed order (deterministic) and publishes mean + sigmoid(wp).
// ---------------------------------------------------------------------------
__global__ void __launch_bounds__(R1_THREADS) k_mean(
    const float4* __restrict__ x4, const float* __restrict__ wp) {
    __shared__ float smem[R1_THREADS / 32];
    __shared__ bool s_last;
    int tid = threadIdx.x;
    int gid = blockIdx.x * R1_THREADS + tid;
    const int stride = R1_BLOCKS * R1_THREADS;   // 262144

    float s = 0.0f;
    #pragma unroll
    for (int i = 0; i < TOTAL4 / stride; i++) {  // 8 iterations, MLP=8
        float4 v = x4[gid + i * stride];
        s += (v.x + v.y) + (v.z + v.w);
    }
    #pragma unroll
    for (int off = 16; off > 0; off >>= 1)
        s += __shfl_down_sync(0xFFFFFFFFu, s, off);
    if ((tid & 31) == 0) smem[tid >> 5] = s;
    __syncthreads();
    if (tid == 0) {
        float t = 0.0f;
        #pragma unroll
        for (int w = 0; w < R1_THREADS / 32; w++) t += smem[w];
        g_partials[blockIdx.x] = t;
        __threadfence();
        unsigned int tk = atomicAdd(&g_ticket, 1u);
        s_last = (tk == R1_BLOCKS - 1);
    }
    __syncthreads();

    if (s_last) {
        float a = 0.0f;
        #pragma unroll
        for (int i = 0; i < R1_BLOCKS / R1_THREADS; i++)
            a += g_partials[tid + i * R1_THREADS];
        #pragma unroll
        for (int off = 16; off > 0; off >>= 1)
            a += __shfl_down_sync(0xFFFFFFFFu, a, off);
        if ((tid & 31) == 0) smem[tid >> 5] = a;
        __syncthreads();
        if (tid == 0) {
            float t = 0.0f;
            #pragma unroll
            for (int w = 0; w < R1_THREADS / 32; w++) t += smem[w];
            g_mean_scale[0] = t * (1.0f / (float)TOTAL);
            g_mean_scale[1] = 1.0f / (1.0f + expf(-wp[0]));
            g_ticket = 0;          // reset for next graph replay
            __threadfence();
        }
    }
}

// ---------------------------------------------------------------------------
// K3: 4 rows per block, 128 threads, each thread owns 8 CONTIGUOUS floats
// of each row. 256-bit loads + 256-bit streaming stores.
// ---------------------------------------------------------------------------
__global__ void __launch_bounds__(K3_THREADS) k_row_norm_tile(
    const float* __restrict__ x, float* __restrict__ out) {
    __shared__ float smem[ROWS_PB][K3_THREADS / 32];
    __shared__ float s_inv[ROWS_PB];
    int tid = threadIdx.x;
    int wid = tid >> 5, lid = tid & 31;
    long long row0 = (long long)blockIdx.x * ROWS_PB;

    float mean  = g_mean_scale[0];
    float scale = g_mean_scale[1];

    // batched 256-bit loads: 4 independent LDG.256
    float v[ROWS_PB][8];
    #pragma unroll
    for (int r = 0; r < ROWS_PB; r++)
        ldg256(x + (row0 + r) * ND + tid * 8, v[r]);

    float ss[ROWS_PB];
    #pragma unroll
    for (int r = 0; r < ROWS_PB; r++) {
        float acc = 0.0f;
        #pragma unroll
        for (int k = 0; k < 8; k++) {
            v[r][k] = fmaxf(v[r][k] - mean, 0.0f);
            acc += v[r][k] * v[r][k];
        }
        ss[r] = acc;
    }

    #pragma unroll
    for (int off = 16; off > 0; off >>= 1) {
        #pragma unroll
        for (int r = 0; r < ROWS_PB; r++)
            ss[r] += __shfl_down_sync(0xFFFFFFFFu, ss[r], off);
    }
    if (lid == 0) {
        #pragma unroll
        for (int r = 0; r < ROWS_PB; r++)
            smem[r][wid] = ss[r];
    }
    __syncthreads();
    if (tid < ROWS_PB) {
        float t = (smem[tid][0] + smem[tid][1]) + (smem[tid][2] + smem[tid][3]);
        s_inv[tid] = scale / fmaxf(sqrtf(t), 1e-12f);
    }
    __syncthreads();

    // 32 independent 256-bit streaming stores per thread
    #pragma unroll
    for (int r = 0; r < ROWS_PB; r++) {
        float inv = s_inv[r];
        float o[8];
        #pragma unroll
        for (int k = 0; k < 8; k++) o[k] = v[r][k] * inv;
        float* orow = out + (row0 + r) * (NG * ND) + tid * 8;
        #pragma unroll
        for (int g = 0; g < NG; g++)
            stg256_cs(orow + g * ND, o);
    }
}

// ---------------------------------------------------------------------------
extern "C" void kernel_launch(void* const* d_in, const int* in_sizes, int n_in,
                              void* d_out, int out_size) {
    const float4* xf = (const float4*)d_in[0];   // [8192, 1024] fp32
    const float*  wp = (const float*)d_in[1];    // [1] fp32
    // d_in[2] = W_tile — structurally kron(ones(1,G), eye(D)): unused.

    k_mean<<<R1_BLOCKS, R1_THREADS>>>(xf, wp);
    k_row_norm_tile<<<NB / ROWS_PB, K3_THREADS>>>((const float*)d_in[0],
                                                  (float*)d_out);
}

// round 8
// speedup vs baseline: 1.1841x; 1.1841x over previous
#include <cuda_runtime.h>
#include <math.h>

#define NB 8192      // batch rows
#define ND 1024      // feature dim
#define NG 8         // tile count
#define TOTAL (NB * ND)          // 8,388,608 floats
#define TOTAL4 (TOTAL / 4)       // 2,097,152 float4
#define R1_BLOCKS 1024
#define R1_THREADS 256
#define ROWS_PB 4                // rows per block in K3

__device__ float g_partials[R1_BLOCKS];
__device__ float g_mean_scale[2];         // [0] = mean, [1] = sigmoid(wp)
__device__ unsigned int g_ticket = 0;     // reset in-kernel each launch

// ---------------------------------------------------------------------------
// K1: per-block partial sums; LAST block reduces the 1024 partials in a
// fixed order (deterministic) and publishes mean + sigmoid(wp).
// Fires the PDL trigger at entry so K3's first wave can begin loading.
// ---------------------------------------------------------------------------
__global__ void __launch_bounds__(R1_THREADS) k_mean(
    const float4* __restrict__ x4, const float* __restrict__ wp) {
    cudaTriggerProgrammaticLaunchCompletion();

    __shared__ float smem[R1_THREADS / 32];
    __shared__ bool s_last;
    int tid = threadIdx.x;
    int gid = blockIdx.x * R1_THREADS + tid;
    const int stride = R1_BLOCKS * R1_THREADS;   // 262144

    float s = 0.0f;
    #pragma unroll
    for (int i = 0; i < TOTAL4 / stride; i++) {  // 8 iterations, MLP=8
        float4 v = x4[gid + i * stride];
        s += (v.x + v.y) + (v.z + v.w);
    }
    #pragma unroll
    for (int off = 16; off > 0; off >>= 1)
        s += __shfl_down_sync(0xFFFFFFFFu, s, off);
    if ((tid & 31) == 0) smem[tid >> 5] = s;
    __syncthreads();
    if (tid == 0) {
        float t = 0.0f;
        #pragma unroll
        for (int w = 0; w < R1_THREADS / 32; w++) t += smem[w];
        g_partials[blockIdx.x] = t;
        __threadfence();
        unsigned int tk = atomicAdd(&g_ticket, 1u);
        s_last = (tk == R1_BLOCKS - 1);
    }
    __syncthreads();

    if (s_last) {
        float a = 0.0f;
        #pragma unroll
        for (int i = 0; i < R1_BLOCKS / R1_THREADS; i++)
            a += g_partials[tid + i * R1_THREADS];
        #pragma unroll
        for (int off = 16; off > 0; off >>= 1)
            a += __shfl_down_sync(0xFFFFFFFFu, a, off);
        if ((tid & 31) == 0) smem[tid >> 5] = a;
        __syncthreads();
        if (tid == 0) {
            float t = 0.0f;
            #pragma unroll
            for (int w = 0; w < R1_THREADS / 32; w++) t += smem[w];
            g_mean_scale[0] = t * (1.0f / (float)TOTAL);
            g_mean_scale[1] = 1.0f / (1.0f + expf(-wp[0]));
            g_ticket = 0;          // reset for next graph replay
            __threadfence();
        }
    }
}

// ---------------------------------------------------------------------------
// K3 (R4-proven shape): 4 rows/block, float4, batched loads, fused reduction,
// streaming stores. PDL: loads issue BEFORE the grid-dependency sync so they
// overlap k_mean's tail; mean is read only after the sync.
// ---------------------------------------------------------------------------
__global__ void __launch_bounds__(256) k_row_norm_tile(
    const float4* __restrict__ x4, float4* __restrict__ out4) {
    __shared__ float smem[ROWS_PB][8];
    __shared__ float s_inv[ROWS_PB];
    int tid = threadIdx.x;                       // 0..255 -> one float4 per row
    long long row0 = (long long)blockIdx.x * ROWS_PB;

    // batched independent loads: MLP = 4 (issued before the PDL sync)
    float4 v[ROWS_PB];
    #pragma unroll
    for (int r = 0; r < ROWS_PB; r++)
        v[r] = x4[(row0 + r) * (ND / 4) + tid];

    cudaGridDependencySynchronize();             // wait for k_mean completion
    float mean  = g_mean_scale[0];
    float scale = g_mean_scale[1];

    float ss[ROWS_PB];
    #pragma unroll
    for (int r = 0; r < ROWS_PB; r++) {
        v[r].x = fmaxf(v[r].x - mean, 0.0f);
        v[r].y = fmaxf(v[r].y - mean, 0.0f);
        v[r].z = fmaxf(v[r].z - mean, 0.0f);
        v[r].w = fmaxf(v[r].w - mean, 0.0f);
        ss[r] = v[r].x * v[r].x + v[r].y * v[r].y
              + v[r].z * v[r].z + v[r].w * v[r].w;
    }

    #pragma unroll
    for (int off = 16; off > 0; off >>= 1) {
        #pragma unroll
        for (int r = 0; r < ROWS_PB; r++)
            ss[r] += __shfl_down_sync(0xFFFFFFFFu, ss[r], off);
    }
    if ((tid & 31) == 0) {
        #pragma unroll
        for (int r = 0; r < ROWS_PB; r++)
            smem[r][tid >> 5] = ss[r];
    }
    __syncthreads();
    if (tid < ROWS_PB) {
        float t = 0.0f;
        #pragma unroll
        for (int w = 0; w < 8; w++) t += smem[tid][w];
        s_inv[tid] = scale / fmaxf(sqrtf(t), 1e-12f);
    }
    __syncthreads();

    // 32 independent streaming stores per thread
    #pragma unroll
    for (int r = 0; r < ROWS_PB; r++) {
        float inv = s_inv[r];
        float4 o;
        o.x = v[r].x * inv; o.y = v[r].y * inv;
        o.z = v[r].z * inv; o.w = v[r].w * inv;
        float4* orow = out4 + (row0 + r) * (NG * ND / 4);
        #pragma unroll
        for (int g = 0; g < NG; g++)
            __stcs(&orow[g * (ND / 4) + tid], o);
    }
}

// ---------------------------------------------------------------------------
extern "C" void kernel_launch(void* const* d_in, const int* in_sizes, int n_in,
                              void* d_out, int out_size) {
    const float4* xf = (const float4*)d_in[0];   // [8192, 1024] fp32
    const float*  wp = (const float*)d_in[1];    // [1] fp32
    // d_in[2] = W_tile — structurally kron(ones(1,G), eye(D)): unused.
    float4* out = (float4*)d_out;                // [8192, 8192] fp32

    k_mean<<<R1_BLOCKS, R1_THREADS>>>(xf, wp);

    // K3 launched with Programmatic Stream Serialization (PDL)
    cudaLaunchConfig_t cfg = {};
    cfg.gridDim  = dim3(NB / ROWS_PB, 1, 1);
    cfg.blockDim = dim3(256, 1, 1);
    cfg.dynamicSmemBytes = 0;
    cfg.stream = 0;
    cudaLaunchAttribute attr[1];
    attr[0].id = cudaLaunchAttributeProgrammaticStreamSerialization;
    attr[0].val.programmaticStreamSerializationAllowed = 1;
    cfg.attrs = attr;
    cfg.numAttrs = 1;
    cudaLaunchKernelEx(&cfg, k_row_norm_tile, xf, out);
}